// round 14
// baseline (speedup 1.0000x reference)
#include <cuda_runtime.h>
#include <cstdint>

#define N_NODES 50000
#define IN_DIM  512
#define HID_DIM 256
#define OUT_DIM 64
#define EDGE_CAP 1700000

#define SCAN_TB 256
#define SCAN_NBLK ((N_NODES + SCAN_TB - 1) / SCAN_TB)   // 196

// ---- scratch (no allocations allowed) ----
__device__ int      g_cnt[N_NODES];
__device__ int      g_rowptr[N_NODES + 1];
__device__ int      g_fill[N_NODES];
__device__ int      g_esrc[EDGE_CAP];
__device__ int      g_part[SCAN_NBLK];
__device__ float    g_dinv[N_NODES];
__device__ uint32_t g_h1b[(size_t)N_NODES * (HID_DIM / 2)];  // bf16x2 packed
__device__ uint32_t g_a1b[(size_t)N_NODES * (HID_DIM / 2)];  // bf16x2 packed
__device__ uint32_t g_h2b[(size_t)N_NODES * (OUT_DIM / 2)];  // bf16x2 packed

// ------------------------------------------------------------------
// helpers
// ------------------------------------------------------------------
static __device__ __forceinline__ uint32_t pack_bf162(float lo, float hi) {
    uint32_t u;
    asm("cvt.rn.bf16x2.f32 %0, %1, %2;" : "=r"(u) : "f"(hi), "f"(lo));
    return u;
}
static __device__ __forceinline__ float bf_lo(uint32_t u) {
    return __uint_as_float(u << 16);
}
static __device__ __forceinline__ float bf_hi(uint32_t u) {
    return __uint_as_float(u & 0xFFFF0000u);
}

// ------------------------------------------------------------------
// CSR build
// ------------------------------------------------------------------
__global__ void count_kernel(const int* __restrict__ dst, int E) {
    int i = blockIdx.x * blockDim.x + threadIdx.x;
    if (i < E) atomicAdd(&g_cnt[dst[i]], 1);
}

__global__ void scan1_kernel() {   // block sums + dinv (fused)
    __shared__ int s[SCAN_TB];
    int t = threadIdx.x;
    int i = blockIdx.x * SCAN_TB + t;
    int v = 0;
    if (i < N_NODES) {
        v = g_cnt[i];
        g_dinv[i] = rsqrtf((float)v + 1.0f);
    }
    s[t] = v;
    __syncthreads();
    for (int off = SCAN_TB / 2; off > 0; off >>= 1) {
        if (t < off) s[t] += s[t + off];
        __syncthreads();
    }
    if (t == 0) g_part[blockIdx.x] = s[0];
}

__global__ void scan2_kernel() {
    __shared__ int s[SCAN_TB];
    int t = threadIdx.x;
    int v = (t < SCAN_NBLK) ? g_part[t] : 0;
    s[t] = v;
    __syncthreads();
    for (int off = 1; off < SCAN_TB; off <<= 1) {
        int u = (t >= off) ? s[t - off] : 0;
        __syncthreads();
        s[t] += u;
        __syncthreads();
    }
    if (t < SCAN_NBLK) g_part[t] = s[t] - v;
    if (t == SCAN_TB - 1) g_rowptr[N_NODES] = s[SCAN_TB - 1];
}

__global__ void scan3_kernel() {
    __shared__ int s[SCAN_TB];
    int t = threadIdx.x;
    int i = blockIdx.x * SCAN_TB + t;
    int v = (i < N_NODES) ? g_cnt[i] : 0;
    s[t] = v;
    __syncthreads();
    for (int off = 1; off < SCAN_TB; off <<= 1) {
        int u = (t >= off) ? s[t - off] : 0;
        __syncthreads();
        s[t] += u;
        __syncthreads();
    }
    if (i < N_NODES) {
        int excl = g_part[blockIdx.x] + s[t] - v;
        g_rowptr[i] = excl;
        g_fill[i]   = excl;
    }
}

__global__ void fill_kernel(const int* __restrict__ src, const int* __restrict__ dst, int E) {
    int i = blockIdx.x * blockDim.x + threadIdx.x;
    if (i < E) {
        int d = dst[i];
        int pos = atomicAdd(&g_fill[d], 1);
        g_esrc[pos] = src[i];
    }
}

// ------------------------------------------------------------------
// GEMM1: bf16 mma.sync m16n8k16, CTA 128x128, BK=16, warp tile 32x64.
// Double-buffered packed-pair smem (stride 12 u32: conflict-free frags).
// A,B converted fp32->bf16 at smem store. Output packed bf16x2.
// (N=256, K=512)
// ------------------------------------------------------------------
#define PSTRIDE 12   // 8 k-pairs + 4 pad (u32)

__global__ void __launch_bounds__(256, 2)
gemm1_bf16_mma(const float* __restrict__ A, const float* __restrict__ B,
               uint32_t* __restrict__ Cb, int M, int N, int K) {
    __shared__ uint32_t Asp[2][128][PSTRIDE];   // [m][kpair]
    __shared__ uint32_t Bsp[2][128][PSTRIDE];   // [n][kpair]

    const int tid  = threadIdx.x;
    const int lane = tid & 31;
    const int w    = tid >> 5;
    const int wm   = w >> 1;              // 0..3
    const int wn   = w & 1;               // 0..1
    const int g    = lane >> 2;           // 0..7
    const int t4   = lane & 3;            // 0..3

    const int row0 = blockIdx.y * 128;
    const int col0 = blockIdx.x * 128;

    const int ar  = tid >> 1;
    const int ap4 = (tid & 1) * 4;        // u32 pair offset 0 or 4
    const int bn_ = tid & 127;
    const int bh4 = (tid >> 7) * 4;

    const int gm = row0 + ar;
    const bool arow_ok = (gm < M);
    const float* aptr = A + (size_t)(arow_ok ? gm : 0) * K + ap4 * 2;
    const float* bcol = B + col0 + bn_;

    float c[2][8][4];
#pragma unroll
    for (int mt = 0; mt < 2; mt++)
#pragma unroll
        for (int nt = 0; nt < 8; nt++)
#pragma unroll
            for (int q = 0; q < 4; q++) c[mt][nt][q] = 0.f;

    // ---- prime buffer 0 ----
    float4 pa0 = make_float4(0.f, 0.f, 0.f, 0.f), pa1 = pa0;
    float pb[8];
    if (arow_ok) { pa0 = *(const float4*)(aptr); pa1 = *(const float4*)(aptr + 4); }
#pragma unroll
    for (int j = 0; j < 4; j++) {
        int k = 2 * (bh4 + j);
        pb[2 * j]     = bcol[(size_t)k * N];
        pb[2 * j + 1] = bcol[(size_t)(k + 1) * N];
    }
    {
        uint32_t* as = &Asp[0][ar][ap4];
        as[0] = pack_bf162(pa0.x, pa0.y); as[1] = pack_bf162(pa0.z, pa0.w);
        as[2] = pack_bf162(pa1.x, pa1.y); as[3] = pack_bf162(pa1.z, pa1.w);
        uint32_t* bs = &Bsp[0][bn_][bh4];
#pragma unroll
        for (int j = 0; j < 4; j++) bs[j] = pack_bf162(pb[2 * j], pb[2 * j + 1]);
    }
    __syncthreads();

    int buf = 0;
    for (int k0 = 0; k0 < K; k0 += 16) {
        const bool has_next = (k0 + 16) < K;
        if (has_next) {
            if (arow_ok) {
                pa0 = *(const float4*)(aptr + k0 + 16);
                pa1 = *(const float4*)(aptr + k0 + 16 + 4);
            }
#pragma unroll
            for (int j = 0; j < 4; j++) {
                int k = k0 + 16 + 2 * (bh4 + j);
                pb[2 * j]     = bcol[(size_t)k * N];
                pb[2 * j + 1] = bcol[(size_t)(k + 1) * N];
            }
        }

        uint32_t af[2][4];
#pragma unroll
        for (int mt = 0; mt < 2; mt++) {
            int rm = wm * 32 + mt * 16;
            af[mt][0] = Asp[buf][rm + g][t4];
            af[mt][1] = Asp[buf][rm + 8 + g][t4];
            af[mt][2] = Asp[buf][rm + g][4 + t4];
            af[mt][3] = Asp[buf][rm + 8 + g][4 + t4];
        }
#pragma unroll
        for (int nt = 0; nt < 8; nt++) {
            int nb = wn * 64 + nt * 8;
            uint32_t b0 = Bsp[buf][nb + g][t4];
            uint32_t b1 = Bsp[buf][nb + g][4 + t4];
#pragma unroll
            for (int mt = 0; mt < 2; mt++) {
                asm volatile(
                    "mma.sync.aligned.m16n8k16.row.col.f32.bf16.bf16.f32 "
                    "{%0,%1,%2,%3}, {%4,%5,%6,%7}, {%8,%9}, {%0,%1,%2,%3};"
                    : "+f"(c[mt][nt][0]), "+f"(c[mt][nt][1]),
                      "+f"(c[mt][nt][2]), "+f"(c[mt][nt][3])
                    : "r"(af[mt][0]), "r"(af[mt][1]), "r"(af[mt][2]), "r"(af[mt][3]),
                      "r"(b0), "r"(b1));
            }
        }

        if (has_next) {
            const int nb = buf ^ 1;
            uint32_t* as = &Asp[nb][ar][ap4];
            as[0] = pack_bf162(pa0.x, pa0.y); as[1] = pack_bf162(pa0.z, pa0.w);
            as[2] = pack_bf162(pa1.x, pa1.y); as[3] = pack_bf162(pa1.z, pa1.w);
            uint32_t* bs = &Bsp[nb][bn_][bh4];
#pragma unroll
            for (int j = 0; j < 4; j++) bs[j] = pack_bf162(pb[2 * j], pb[2 * j + 1]);
            __syncthreads();
            buf = nb;
        }
    }

#pragma unroll
    for (int mt = 0; mt < 2; mt++) {
#pragma unroll
        for (int nt = 0; nt < 8; nt++) {
            int rbase = row0 + wm * 32 + mt * 16 + g;
            int cpair = (col0 + wn * 64 + nt * 8 + 2 * t4) >> 1;
            if (rbase < M)
                Cb[(size_t)rbase * (N / 2) + cpair] = pack_bf162(c[mt][nt][0], c[mt][nt][1]);
            if (rbase + 8 < M)
                Cb[(size_t)(rbase + 8) * (N / 2) + cpair] = pack_bf162(c[mt][nt][2], c[mt][nt][3]);
        }
    }
}

// ------------------------------------------------------------------
// GEMM2: bf16 mma.sync m16n8k16, CTA 128x64, warp tile 32x32.
// A arrives ALREADY packed bf16x2 (a1b). Double-buffered with
// register prefetch: one __syncthreads per K-slab. (N=64, K=256)
// ------------------------------------------------------------------
__global__ void __launch_bounds__(256, 2)
gemm2_bf16_mma(const uint32_t* __restrict__ Ab, const float* __restrict__ B,
               uint32_t* __restrict__ Cb, int M) {
    const int N = OUT_DIM, K = HID_DIM;
    __shared__ uint32_t Asp[2][128][PSTRIDE];
    __shared__ uint32_t Bsp[2][64][PSTRIDE];

    const int tid  = threadIdx.x;
    const int lane = tid & 31;
    const int w    = tid >> 5;
    const int wm   = w >> 1;
    const int wn   = w & 1;
    const int g    = lane >> 2;
    const int t4   = lane & 3;

    const int row0 = blockIdx.x * 128;

    const int ar  = tid >> 1;
    const int ap4 = (tid & 1) * 4;
    const int bn_ = tid & 63;
    const int bq  = tid >> 6;

    const int gm = row0 + ar;
    const bool arow_ok = (gm < M);
    const uint32_t* aptr = Ab + (size_t)(arow_ok ? gm : 0) * (K / 2) + ap4;
    const float* bcol = B + bn_;

    float c[2][4][4];
#pragma unroll
    for (int mt = 0; mt < 2; mt++)
#pragma unroll
        for (int nt = 0; nt < 4; nt++)
#pragma unroll
            for (int q = 0; q < 4; q++) c[mt][nt][q] = 0.f;

    // ---- prime buffer 0 ----
    uint4 av = make_uint4(0u, 0u, 0u, 0u);
    float pf[4];
    if (arow_ok) av = *(const uint4*)(aptr);
#pragma unroll
    for (int j = 0; j < 2; j++) {
        int kp = bq + 4 * j;
        int k = 2 * kp;
        pf[2 * j]     = bcol[(size_t)k * N];
        pf[2 * j + 1] = bcol[(size_t)(k + 1) * N];
    }
    {
        uint32_t* as = &Asp[0][ar][ap4];
        as[0] = av.x; as[1] = av.y; as[2] = av.z; as[3] = av.w;
#pragma unroll
        for (int j = 0; j < 2; j++)
            Bsp[0][bn_][bq + 4 * j] = pack_bf162(pf[2 * j], pf[2 * j + 1]);
    }
    __syncthreads();

    int buf = 0;
    for (int k0 = 0; k0 < K; k0 += 16) {
        const bool has_next = (k0 + 16) < K;
        if (has_next) {
            if (arow_ok) av = *(const uint4*)(aptr + (k0 + 16) / 2);
#pragma unroll
            for (int j = 0; j < 2; j++) {
                int kp = bq + 4 * j;
                int k = k0 + 16 + 2 * kp;
                pf[2 * j]     = bcol[(size_t)k * N];
                pf[2 * j + 1] = bcol[(size_t)(k + 1) * N];
            }
        }

        uint32_t af[2][4];
#pragma unroll
        for (int mt = 0; mt < 2; mt++) {
            int rm = wm * 32 + mt * 16;
            af[mt][0] = Asp[buf][rm + g][t4];
            af[mt][1] = Asp[buf][rm + 8 + g][t4];
            af[mt][2] = Asp[buf][rm + g][4 + t4];
            af[mt][3] = Asp[buf][rm + 8 + g][4 + t4];
        }
#pragma unroll
        for (int nt = 0; nt < 4; nt++) {
            int nb = wn * 32 + nt * 8;
            uint32_t b0 = Bsp[buf][nb + g][t4];
            uint32_t b1 = Bsp[buf][nb + g][4 + t4];
#pragma unroll
            for (int mt = 0; mt < 2; mt++) {
                asm volatile(
                    "mma.sync.aligned.m16n8k16.row.col.f32.bf16.bf16.f32 "
                    "{%0,%1,%2,%3}, {%4,%5,%6,%7}, {%8,%9}, {%0,%1,%2,%3};"
                    : "+f"(c[mt][nt][0]), "+f"(c[mt][nt][1]),
                      "+f"(c[mt][nt][2]), "+f"(c[mt][nt][3])
                    : "r"(af[mt][0]), "r"(af[mt][1]), "r"(af[mt][2]), "r"(af[mt][3]),
                      "r"(b0), "r"(b1));
            }
        }

        if (has_next) {
            const int nb = buf ^ 1;
            uint32_t* as = &Asp[nb][ar][ap4];
            as[0] = av.x; as[1] = av.y; as[2] = av.z; as[3] = av.w;
#pragma unroll
            for (int j = 0; j < 2; j++)
                Bsp[nb][bn_][bq + 4 * j] = pack_bf162(pf[2 * j], pf[2 * j + 1]);
            __syncthreads();
            buf = nb;
        }
    }

#pragma unroll
    for (int mt = 0; mt < 2; mt++) {
#pragma unroll
        for (int nt = 0; nt < 4; nt++) {
            int rbase = row0 + wm * 32 + mt * 16 + g;
            int cpair = (wn * 32 + nt * 8 + 2 * t4) >> 1;
            if (rbase < M)
                Cb[(size_t)rbase * (N / 2) + cpair] = pack_bf162(c[mt][nt][0], c[mt][nt][1]);
            if (rbase + 8 < M)
                Cb[(size_t)(rbase + 8) * (N / 2) + cpair] = pack_bf162(c[mt][nt][2], c[mt][nt][3]);
        }
    }
}

// ------------------------------------------------------------------
// Layer-1 aggregation (bf16 gather, 4-edge unroll) + self+bias+relu
// ------------------------------------------------------------------
__global__ void spmm_relu_bf16(const uint32_t* __restrict__ h, uint32_t* __restrict__ outb,
                               const float* __restrict__ b1) {
    const int node = (blockIdx.x * blockDim.x + threadIdx.x) >> 5;
    const int lane = threadIdx.x & 31;
    if (node >= N_NODES) return;
    const int beg = g_rowptr[node];
    const int end = g_rowptr[node + 1];

    float acc[8] = {};
    int e = beg;
    for (; e + 3 < end; e += 4) {
        int s0 = __ldg(&g_esrc[e]);
        int s1 = __ldg(&g_esrc[e + 1]);
        int s2 = __ldg(&g_esrc[e + 2]);
        int s3 = __ldg(&g_esrc[e + 3]);
        float w0 = __ldg(&g_dinv[s0]);
        float w1 = __ldg(&g_dinv[s1]);
        float w2 = __ldg(&g_dinv[s2]);
        float w3 = __ldg(&g_dinv[s3]);
        uint4 v0 = __ldg((const uint4*)(h + (size_t)s0 * (HID_DIM / 2)) + lane);
        uint4 v1 = __ldg((const uint4*)(h + (size_t)s1 * (HID_DIM / 2)) + lane);
        uint4 v2 = __ldg((const uint4*)(h + (size_t)s2 * (HID_DIM / 2)) + lane);
        uint4 v3 = __ldg((const uint4*)(h + (size_t)s3 * (HID_DIM / 2)) + lane);
        acc[0] += w0 * bf_lo(v0.x) + w1 * bf_lo(v1.x) + w2 * bf_lo(v2.x) + w3 * bf_lo(v3.x);
        acc[1] += w0 * bf_hi(v0.x) + w1 * bf_hi(v1.x) + w2 * bf_hi(v2.x) + w3 * bf_hi(v3.x);
        acc[2] += w0 * bf_lo(v0.y) + w1 * bf_lo(v1.y) + w2 * bf_lo(v2.y) + w3 * bf_lo(v3.y);
        acc[3] += w0 * bf_hi(v0.y) + w1 * bf_hi(v1.y) + w2 * bf_hi(v2.y) + w3 * bf_hi(v3.y);
        acc[4] += w0 * bf_lo(v0.z) + w1 * bf_lo(v1.z) + w2 * bf_lo(v2.z) + w3 * bf_lo(v3.z);
        acc[5] += w0 * bf_hi(v0.z) + w1 * bf_hi(v1.z) + w2 * bf_hi(v2.z) + w3 * bf_hi(v3.z);
        acc[6] += w0 * bf_lo(v0.w) + w1 * bf_lo(v1.w) + w2 * bf_lo(v2.w) + w3 * bf_lo(v3.w);
        acc[7] += w0 * bf_hi(v0.w) + w1 * bf_hi(v1.w) + w2 * bf_hi(v2.w) + w3 * bf_hi(v3.w);
    }
    for (; e < end; e++) {
        int s0 = __ldg(&g_esrc[e]);
        float w0 = __ldg(&g_dinv[s0]);
        uint4 v0 = __ldg((const uint4*)(h + (size_t)s0 * (HID_DIM / 2)) + lane);
        acc[0] += w0 * bf_lo(v0.x); acc[1] += w0 * bf_hi(v0.x);
        acc[2] += w0 * bf_lo(v0.y); acc[3] += w0 * bf_hi(v0.y);
        acc[4] += w0 * bf_lo(v0.z); acc[5] += w0 * bf_hi(v0.z);
        acc[6] += w0 * bf_lo(v0.w); acc[7] += w0 * bf_hi(v0.w);
    }

    float di = g_dinv[node];
    float sw = di * di;
    uint4 sv = __ldg((const uint4*)(h + (size_t)node * (HID_DIM / 2)) + lane);
    float4 bia0 = __ldg((const float4*)b1 + 2 * lane);
    float4 bia1 = __ldg((const float4*)b1 + 2 * lane + 1);

    float r0 = fmaxf(di * acc[0] + sw * bf_lo(sv.x) + bia0.x, 0.f);
    float r1 = fmaxf(di * acc[1] + sw * bf_hi(sv.x) + bia0.y, 0.f);
    float r2 = fmaxf(di * acc[2] + sw * bf_lo(sv.y) + bia0.z, 0.f);
    float r3 = fmaxf(di * acc[3] + sw * bf_hi(sv.y) + bia0.w, 0.f);
    float r4 = fmaxf(di * acc[4] + sw * bf_lo(sv.z) + bia1.x, 0.f);
    float r5 = fmaxf(di * acc[5] + sw * bf_hi(sv.z) + bia1.y, 0.f);
    float r6 = fmaxf(di * acc[6] + sw * bf_lo(sv.w) + bia1.z, 0.f);
    float r7 = fmaxf(di * acc[7] + sw * bf_hi(sv.w) + bia1.w, 0.f);

    uint4 rv;
    rv.x = pack_bf162(r0, r1);
    rv.y = pack_bf162(r2, r3);
    rv.z = pack_bf162(r4, r5);
    rv.w = pack_bf162(r6, r7);
    ((uint4*)(outb + (size_t)node * (HID_DIM / 2)))[lane] = rv;
}

// ------------------------------------------------------------------
// Layer-2 aggregation (bf16 gather, 4-edge unroll) + bias + log_softmax
// ------------------------------------------------------------------
__global__ void spmm_softmax_bf16(const uint32_t* __restrict__ h, float* __restrict__ out,
                                  const float* __restrict__ b2) {
    const int node = (blockIdx.x * blockDim.x + threadIdx.x) >> 5;
    const int lane = threadIdx.x & 31;
    if (node >= N_NODES) return;

    const int beg = g_rowptr[node];
    const int end = g_rowptr[node + 1];

    float a0 = 0.f, a1 = 0.f;
    int e = beg;
    for (; e + 3 < end; e += 4) {
        int s0 = __ldg(&g_esrc[e]);
        int s1 = __ldg(&g_esrc[e + 1]);
        int s2 = __ldg(&g_esrc[e + 2]);
        int s3 = __ldg(&g_esrc[e + 3]);
        float w0 = __ldg(&g_dinv[s0]);
        float w1 = __ldg(&g_dinv[s1]);
        float w2 = __ldg(&g_dinv[s2]);
        float w3 = __ldg(&g_dinv[s3]);
        uint32_t v0 = __ldg(h + (size_t)s0 * (OUT_DIM / 2) + lane);
        uint32_t v1 = __ldg(h + (size_t)s1 * (OUT_DIM / 2) + lane);
        uint32_t v2 = __ldg(h + (size_t)s2 * (OUT_DIM / 2) + lane);
        uint32_t v3 = __ldg(h + (size_t)s3 * (OUT_DIM / 2) + lane);
        a0 += w0 * bf_lo(v0) + w1 * bf_lo(v1) + w2 * bf_lo(v2) + w3 * bf_lo(v3);
        a1 += w0 * bf_hi(v0) + w1 * bf_hi(v1) + w2 * bf_hi(v2) + w3 * bf_hi(v3);
    }
    for (; e < end; e++) {
        int s0 = __ldg(&g_esrc[e]);
        float w0 = __ldg(&g_dinv[s0]);
        uint32_t v0 = __ldg(h + (size_t)s0 * (OUT_DIM / 2) + lane);
        a0 += w0 * bf_lo(v0);
        a1 += w0 * bf_hi(v0);
    }

    float di = g_dinv[node];
    float sw = di * di;
    uint32_t sv = __ldg(h + (size_t)node * (OUT_DIM / 2) + lane);
    float2 bias = __ldg((const float2*)b2 + lane);
    float v0 = di * a0 + sw * bf_lo(sv) + bias.x;
    float v1 = di * a1 + sw * bf_hi(sv) + bias.y;

    float m = fmaxf(v0, v1);
#pragma unroll
    for (int o = 16; o; o >>= 1) m = fmaxf(m, __shfl_xor_sync(0xFFFFFFFFu, m, o));
    float s = expf(v0 - m) + expf(v1 - m);
#pragma unroll
    for (int o = 16; o; o >>= 1) s += __shfl_xor_sync(0xFFFFFFFFu, s, o);
    float ls = m + logf(s);

    ((float2*)(out + (size_t)node * OUT_DIM))[lane] = make_float2(v0 - ls, v1 - ls);
}

// ------------------------------------------------------------------
extern "C" void kernel_launch(void* const* d_in, const int* in_sizes, int n_in,
                              void* d_out, int out_size) {
    const float* x  = (const float*)d_in[0];
    const float* W1 = (const float*)d_in[1];
    const float* b1 = (const float*)d_in[2];
    const float* W2 = (const float*)d_in[3];
    const float* b2 = (const float*)d_in[4];
    const int* ei   = (const int*)d_in[5];
    const int E = in_sizes[5] / 2;
    const int* src = ei;
    const int* dst = ei + E;
    float* out = (float*)d_out;

    uint32_t *h1b, *a1b, *h2b;
    int* cntp;
    cudaGetSymbolAddress((void**)&h1b, g_h1b);
    cudaGetSymbolAddress((void**)&a1b, g_a1b);
    cudaGetSymbolAddress((void**)&h2b, g_h2b);
    cudaGetSymbolAddress((void**)&cntp, g_cnt);

    // Host-side stream/events, created once on the (non-captured) correctness
    // call. Capture-legal fork/join pattern thereafter.
    static cudaStream_t s_side = nullptr;
    static cudaEvent_t s_evFork = nullptr, s_evJoin = nullptr;
    if (s_side == nullptr) {
        cudaStreamCreateWithFlags(&s_side, cudaStreamNonBlocking);
        cudaEventCreateWithFlags(&s_evFork, cudaEventDisableTiming);
        cudaEventCreateWithFlags(&s_evJoin, cudaEventDisableTiming);
    }

    const int TB = 256;

    // ---- fork: CSR build on side stream, GEMM1 on main stream ----
    cudaEventRecord(s_evFork, 0);
    cudaStreamWaitEvent(s_side, s_evFork, 0);

    cudaMemsetAsync(cntp, 0, N_NODES * sizeof(int), s_side);
    count_kernel<<<(E + TB - 1) / TB, TB, 0, s_side>>>(dst, E);
    scan1_kernel<<<SCAN_NBLK, SCAN_TB, 0, s_side>>>();       // also computes dinv
    scan2_kernel<<<1, SCAN_TB, 0, s_side>>>();
    scan3_kernel<<<SCAN_NBLK, SCAN_TB, 0, s_side>>>();
    fill_kernel<<<(E + TB - 1) / TB, TB, 0, s_side>>>(src, dst, E);
    cudaEventRecord(s_evJoin, s_side);

    // main stream: h1 = bf16(x @ W1), independent of CSR
    gemm1_bf16_mma<<<dim3(HID_DIM / 128, (N_NODES + 127) / 128), 256>>>(
        x, W1, h1b, N_NODES, HID_DIM, IN_DIM);

    // ---- join, then the dependent chain ----
    cudaStreamWaitEvent(0, s_evJoin, 0);
    spmm_relu_bf16<<<(N_NODES * 32 + TB - 1) / TB, TB>>>(h1b, a1b, b1);
    gemm2_bf16_mma<<<(N_NODES + 127) / 128, 256>>>(a1b, W2, h2b, N_NODES);
    spmm_softmax_bf16<<<(N_NODES * 32 + TB - 1) / TB, TB>>>(h2b, out, b2);
}

// round 15
// speedup vs baseline: 1.0366x; 1.0366x over previous
#include <cuda_runtime.h>
#include <cstdint>

#define N_NODES 50000
#define IN_DIM  512
#define HID_DIM 256
#define OUT_DIM 64
#define EDGE_CAP 1700000

#define SCAN_TB 256
#define SCAN_NBLK ((N_NODES + SCAN_TB - 1) / SCAN_TB)   // 196

// ---- scratch (no allocations allowed) ----
__device__ int      g_cnt[N_NODES];
__device__ int      g_rowptr[N_NODES + 1];
__device__ int      g_fill[N_NODES];
__device__ int      g_esrc[EDGE_CAP];
__device__ int      g_part[SCAN_NBLK];
__device__ float    g_dinv[N_NODES];
__device__ uint32_t g_h1b[(size_t)N_NODES * (HID_DIM / 2)];  // bf16x2 packed
__device__ uint32_t g_a1b[(size_t)N_NODES * (HID_DIM / 2)];  // bf16x2 packed
__device__ uint32_t g_h2b[(size_t)N_NODES * (OUT_DIM / 2)];  // bf16x2 packed

// ------------------------------------------------------------------
// helpers
// ------------------------------------------------------------------
static __device__ __forceinline__ uint32_t pack_bf162(float lo, float hi) {
    uint32_t u;
    asm("cvt.rn.bf16x2.f32 %0, %1, %2;" : "=r"(u) : "f"(hi), "f"(lo));
    return u;
}
static __device__ __forceinline__ float bf_lo(uint32_t u) {
    return __uint_as_float(u << 16);
}
static __device__ __forceinline__ float bf_hi(uint32_t u) {
    return __uint_as_float(u & 0xFFFF0000u);
}

// ------------------------------------------------------------------
// CSR build
// ------------------------------------------------------------------
__global__ void count_kernel(const int* __restrict__ dst, int E) {
    int i = blockIdx.x * blockDim.x + threadIdx.x;
    if (i < E) atomicAdd(&g_cnt[dst[i]], 1);
}

__global__ void scan1_kernel() {   // block sums + dinv (fused)
    __shared__ int s[SCAN_TB];
    int t = threadIdx.x;
    int i = blockIdx.x * SCAN_TB + t;
    int v = 0;
    if (i < N_NODES) {
        v = g_cnt[i];
        g_dinv[i] = rsqrtf((float)v + 1.0f);
    }
    s[t] = v;
    __syncthreads();
    for (int off = SCAN_TB / 2; off > 0; off >>= 1) {
        if (t < off) s[t] += s[t + off];
        __syncthreads();
    }
    if (t == 0) g_part[blockIdx.x] = s[0];
}

__global__ void scan2_kernel() {
    __shared__ int s[SCAN_TB];
    int t = threadIdx.x;
    int v = (t < SCAN_NBLK) ? g_part[t] : 0;
    s[t] = v;
    __syncthreads();
    for (int off = 1; off < SCAN_TB; off <<= 1) {
        int u = (t >= off) ? s[t - off] : 0;
        __syncthreads();
        s[t] += u;
        __syncthreads();
    }
    if (t < SCAN_NBLK) g_part[t] = s[t] - v;
    if (t == SCAN_TB - 1) g_rowptr[N_NODES] = s[SCAN_TB - 1];
}

__global__ void scan3_kernel() {
    __shared__ int s[SCAN_TB];
    int t = threadIdx.x;
    int i = blockIdx.x * SCAN_TB + t;
    int v = (i < N_NODES) ? g_cnt[i] : 0;
    s[t] = v;
    __syncthreads();
    for (int off = 1; off < SCAN_TB; off <<= 1) {
        int u = (t >= off) ? s[t - off] : 0;
        __syncthreads();
        s[t] += u;
        __syncthreads();
    }
    if (i < N_NODES) {
        int excl = g_part[blockIdx.x] + s[t] - v;
        g_rowptr[i] = excl;
        g_fill[i]   = excl;
    }
}

__global__ void fill_kernel(const int* __restrict__ src, const int* __restrict__ dst, int E) {
    int i = blockIdx.x * blockDim.x + threadIdx.x;
    if (i < E) {
        int d = dst[i];
        int pos = atomicAdd(&g_fill[d], 1);
        g_esrc[pos] = src[i];
    }
}

// ------------------------------------------------------------------
// GEMM1: bf16 mma.sync m16n8k16, CTA 128x128, BK=16, warp tile 32x64.
// Double-buffered packed-pair smem (stride 12 u32: conflict-free frags).
// A,B converted fp32->bf16 at smem store. Output packed bf16x2.
// (N=256, K=512)
// ------------------------------------------------------------------
#define PSTRIDE 12   // 8 k-pairs + 4 pad (u32)

__global__ void __launch_bounds__(256, 2)
gemm1_bf16_mma(const float* __restrict__ A, const float* __restrict__ B,
               uint32_t* __restrict__ Cb, int M, int N, int K) {
    __shared__ uint32_t Asp[2][128][PSTRIDE];   // [m][kpair]
    __shared__ uint32_t Bsp[2][128][PSTRIDE];   // [n][kpair]

    const int tid  = threadIdx.x;
    const int lane = tid & 31;
    const int w    = tid >> 5;
    const int wm   = w >> 1;              // 0..3
    const int wn   = w & 1;               // 0..1
    const int g    = lane >> 2;           // 0..7
    const int t4   = lane & 3;            // 0..3

    const int row0 = blockIdx.y * 128;
    const int col0 = blockIdx.x * 128;

    const int ar  = tid >> 1;
    const int ap4 = (tid & 1) * 4;        // u32 pair offset 0 or 4
    const int bn_ = tid & 127;
    const int bh4 = (tid >> 7) * 4;

    const int gm = row0 + ar;
    const bool arow_ok = (gm < M);
    const float* aptr = A + (size_t)(arow_ok ? gm : 0) * K + ap4 * 2;
    const float* bcol = B + col0 + bn_;

    float c[2][8][4];
#pragma unroll
    for (int mt = 0; mt < 2; mt++)
#pragma unroll
        for (int nt = 0; nt < 8; nt++)
#pragma unroll
            for (int q = 0; q < 4; q++) c[mt][nt][q] = 0.f;

    // ---- prime buffer 0 ----
    float4 pa0 = make_float4(0.f, 0.f, 0.f, 0.f), pa1 = pa0;
    float pb[8];
    if (arow_ok) { pa0 = *(const float4*)(aptr); pa1 = *(const float4*)(aptr + 4); }
#pragma unroll
    for (int j = 0; j < 4; j++) {
        int k = 2 * (bh4 + j);
        pb[2 * j]     = bcol[(size_t)k * N];
        pb[2 * j + 1] = bcol[(size_t)(k + 1) * N];
    }
    {
        uint32_t* as = &Asp[0][ar][ap4];
        as[0] = pack_bf162(pa0.x, pa0.y); as[1] = pack_bf162(pa0.z, pa0.w);
        as[2] = pack_bf162(pa1.x, pa1.y); as[3] = pack_bf162(pa1.z, pa1.w);
        uint32_t* bs = &Bsp[0][bn_][bh4];
#pragma unroll
        for (int j = 0; j < 4; j++) bs[j] = pack_bf162(pb[2 * j], pb[2 * j + 1]);
    }
    __syncthreads();

    int buf = 0;
    for (int k0 = 0; k0 < K; k0 += 16) {
        const bool has_next = (k0 + 16) < K;
        if (has_next) {
            if (arow_ok) {
                pa0 = *(const float4*)(aptr + k0 + 16);
                pa1 = *(const float4*)(aptr + k0 + 16 + 4);
            }
#pragma unroll
            for (int j = 0; j < 4; j++) {
                int k = k0 + 16 + 2 * (bh4 + j);
                pb[2 * j]     = bcol[(size_t)k * N];
                pb[2 * j + 1] = bcol[(size_t)(k + 1) * N];
            }
        }

        uint32_t af[2][4];
#pragma unroll
        for (int mt = 0; mt < 2; mt++) {
            int rm = wm * 32 + mt * 16;
            af[mt][0] = Asp[buf][rm + g][t4];
            af[mt][1] = Asp[buf][rm + 8 + g][t4];
            af[mt][2] = Asp[buf][rm + g][4 + t4];
            af[mt][3] = Asp[buf][rm + 8 + g][4 + t4];
        }
#pragma unroll
        for (int nt = 0; nt < 8; nt++) {
            int nb = wn * 64 + nt * 8;
            uint32_t b0 = Bsp[buf][nb + g][t4];
            uint32_t b1 = Bsp[buf][nb + g][4 + t4];
#pragma unroll
            for (int mt = 0; mt < 2; mt++) {
                asm volatile(
                    "mma.sync.aligned.m16n8k16.row.col.f32.bf16.bf16.f32 "
                    "{%0,%1,%2,%3}, {%4,%5,%6,%7}, {%8,%9}, {%0,%1,%2,%3};"
                    : "+f"(c[mt][nt][0]), "+f"(c[mt][nt][1]),
                      "+f"(c[mt][nt][2]), "+f"(c[mt][nt][3])
                    : "r"(af[mt][0]), "r"(af[mt][1]), "r"(af[mt][2]), "r"(af[mt][3]),
                      "r"(b0), "r"(b1));
            }
        }

        if (has_next) {
            const int nb = buf ^ 1;
            uint32_t* as = &Asp[nb][ar][ap4];
            as[0] = pack_bf162(pa0.x, pa0.y); as[1] = pack_bf162(pa0.z, pa0.w);
            as[2] = pack_bf162(pa1.x, pa1.y); as[3] = pack_bf162(pa1.z, pa1.w);
            uint32_t* bs = &Bsp[nb][bn_][bh4];
#pragma unroll
            for (int j = 0; j < 4; j++) bs[j] = pack_bf162(pb[2 * j], pb[2 * j + 1]);
            __syncthreads();
            buf = nb;
        }
    }

#pragma unroll
    for (int mt = 0; mt < 2; mt++) {
#pragma unroll
        for (int nt = 0; nt < 8; nt++) {
            int rbase = row0 + wm * 32 + mt * 16 + g;
            int cpair = (col0 + wn * 64 + nt * 8 + 2 * t4) >> 1;
            if (rbase < M)
                Cb[(size_t)rbase * (N / 2) + cpair] = pack_bf162(c[mt][nt][0], c[mt][nt][1]);
            if (rbase + 8 < M)
                Cb[(size_t)(rbase + 8) * (N / 2) + cpair] = pack_bf162(c[mt][nt][2], c[mt][nt][3]);
        }
    }
}

// ------------------------------------------------------------------
// GEMM2: bf16 mma.sync m16n8k16, CTA 128x64, warp tile 32x32.
// A arrives ALREADY packed bf16x2 (a1b). (N=64, K=256)
// ------------------------------------------------------------------
__global__ void __launch_bounds__(256, 2)
gemm2_bf16_mma(const uint32_t* __restrict__ Ab, const float* __restrict__ B,
               uint32_t* __restrict__ Cb, int M) {
    const int N = OUT_DIM, K = HID_DIM;
    __shared__ uint32_t Asp[128][PSTRIDE];
    __shared__ uint32_t Bsp[64][PSTRIDE];

    const int tid  = threadIdx.x;
    const int lane = tid & 31;
    const int w    = tid >> 5;
    const int wm   = w >> 1;
    const int wn   = w & 1;
    const int g    = lane >> 2;
    const int t4   = lane & 3;

    const int row0 = blockIdx.x * 128;

    const int ar  = tid >> 1;
    const int ap4 = (tid & 1) * 4;
    const int bn_ = tid & 63;
    const int bq  = tid >> 6;

    const int gm = row0 + ar;
    const bool arow_ok = (gm < M);
    const uint32_t* aptr = Ab + (size_t)(arow_ok ? gm : 0) * (K / 2) + ap4;
    const float* bcol = B + bn_;

    float c[2][4][4];
#pragma unroll
    for (int mt = 0; mt < 2; mt++)
#pragma unroll
        for (int nt = 0; nt < 4; nt++)
#pragma unroll
            for (int q = 0; q < 4; q++) c[mt][nt][q] = 0.f;

    for (int k0 = 0; k0 < K; k0 += 16) {
        {
            uint4 av = make_uint4(0u, 0u, 0u, 0u);
            if (arow_ok) av = *(const uint4*)(aptr + k0 / 2);
            uint32_t* as = &Asp[ar][ap4];
            as[0] = av.x; as[1] = av.y; as[2] = av.z; as[3] = av.w;
        }
        {
#pragma unroll
            for (int j = 0; j < 2; j++) {
                int kp = bq + 4 * j;
                int k = k0 + 2 * kp;
                float f0 = bcol[(size_t)k * N];
                float f1 = bcol[(size_t)(k + 1) * N];
                Bsp[bn_][kp] = pack_bf162(f0, f1);
            }
        }
        __syncthreads();

        uint32_t af[2][4];
#pragma unroll
        for (int mt = 0; mt < 2; mt++) {
            int rm = wm * 32 + mt * 16;
            af[mt][0] = Asp[rm + g][t4];
            af[mt][1] = Asp[rm + 8 + g][t4];
            af[mt][2] = Asp[rm + g][4 + t4];
            af[mt][3] = Asp[rm + 8 + g][4 + t4];
        }
#pragma unroll
        for (int nt = 0; nt < 4; nt++) {
            int nb = wn * 32 + nt * 8;
            uint32_t b0 = Bsp[nb + g][t4];
            uint32_t b1 = Bsp[nb + g][4 + t4];
#pragma unroll
            for (int mt = 0; mt < 2; mt++) {
                asm volatile(
                    "mma.sync.aligned.m16n8k16.row.col.f32.bf16.bf16.f32 "
                    "{%0,%1,%2,%3}, {%4,%5,%6,%7}, {%8,%9}, {%0,%1,%2,%3};"
                    : "+f"(c[mt][nt][0]), "+f"(c[mt][nt][1]),
                      "+f"(c[mt][nt][2]), "+f"(c[mt][nt][3])
                    : "r"(af[mt][0]), "r"(af[mt][1]), "r"(af[mt][2]), "r"(af[mt][3]),
                      "r"(b0), "r"(b1));
            }
        }
        __syncthreads();
    }

#pragma unroll
    for (int mt = 0; mt < 2; mt++) {
#pragma unroll
        for (int nt = 0; nt < 4; nt++) {
            int rbase = row0 + wm * 32 + mt * 16 + g;
            int cpair = (wn * 32 + nt * 8 + 2 * t4) >> 1;
            if (rbase < M)
                Cb[(size_t)rbase * (N / 2) + cpair] = pack_bf162(c[mt][nt][0], c[mt][nt][1]);
            if (rbase + 8 < M)
                Cb[(size_t)(rbase + 8) * (N / 2) + cpair] = pack_bf162(c[mt][nt][2], c[mt][nt][3]);
        }
    }
}

// ------------------------------------------------------------------
// Layer-1 aggregation (bf16 gather, 4-edge unroll) + self+bias+relu
// ------------------------------------------------------------------
__global__ void spmm_relu_bf16(const uint32_t* __restrict__ h, uint32_t* __restrict__ outb,
                               const float* __restrict__ b1) {
    const int node = (blockIdx.x * blockDim.x + threadIdx.x) >> 5;
    const int lane = threadIdx.x & 31;
    if (node >= N_NODES) return;
    const int beg = g_rowptr[node];
    const int end = g_rowptr[node + 1];

    float acc[8] = {};
    int e = beg;
    for (; e + 3 < end; e += 4) {
        int s0 = __ldg(&g_esrc[e]);
        int s1 = __ldg(&g_esrc[e + 1]);
        int s2 = __ldg(&g_esrc[e + 2]);
        int s3 = __ldg(&g_esrc[e + 3]);
        float w0 = __ldg(&g_dinv[s0]);
        float w1 = __ldg(&g_dinv[s1]);
        float w2 = __ldg(&g_dinv[s2]);
        float w3 = __ldg(&g_dinv[s3]);
        uint4 v0 = __ldg((const uint4*)(h + (size_t)s0 * (HID_DIM / 2)) + lane);
        uint4 v1 = __ldg((const uint4*)(h + (size_t)s1 * (HID_DIM / 2)) + lane);
        uint4 v2 = __ldg((const uint4*)(h + (size_t)s2 * (HID_DIM / 2)) + lane);
        uint4 v3 = __ldg((const uint4*)(h + (size_t)s3 * (HID_DIM / 2)) + lane);
        acc[0] += w0 * bf_lo(v0.x) + w1 * bf_lo(v1.x) + w2 * bf_lo(v2.x) + w3 * bf_lo(v3.x);
        acc[1] += w0 * bf_hi(v0.x) + w1 * bf_hi(v1.x) + w2 * bf_hi(v2.x) + w3 * bf_hi(v3.x);
        acc[2] += w0 * bf_lo(v0.y) + w1 * bf_lo(v1.y) + w2 * bf_lo(v2.y) + w3 * bf_lo(v3.y);
        acc[3] += w0 * bf_hi(v0.y) + w1 * bf_hi(v1.y) + w2 * bf_hi(v2.y) + w3 * bf_hi(v3.y);
        acc[4] += w0 * bf_lo(v0.z) + w1 * bf_lo(v1.z) + w2 * bf_lo(v2.z) + w3 * bf_lo(v3.z);
        acc[5] += w0 * bf_hi(v0.z) + w1 * bf_hi(v1.z) + w2 * bf_hi(v2.z) + w3 * bf_hi(v3.z);
        acc[6] += w0 * bf_lo(v0.w) + w1 * bf_lo(v1.w) + w2 * bf_lo(v2.w) + w3 * bf_lo(v3.w);
        acc[7] += w0 * bf_hi(v0.w) + w1 * bf_hi(v1.w) + w2 * bf_hi(v2.w) + w3 * bf_hi(v3.w);
    }
    for (; e < end; e++) {
        int s0 = __ldg(&g_esrc[e]);
        float w0 = __ldg(&g_dinv[s0]);
        uint4 v0 = __ldg((const uint4*)(h + (size_t)s0 * (HID_DIM / 2)) + lane);
        acc[0] += w0 * bf_lo(v0.x); acc[1] += w0 * bf_hi(v0.x);
        acc[2] += w0 * bf_lo(v0.y); acc[3] += w0 * bf_hi(v0.y);
        acc[4] += w0 * bf_lo(v0.z); acc[5] += w0 * bf_hi(v0.z);
        acc[6] += w0 * bf_lo(v0.w); acc[7] += w0 * bf_hi(v0.w);
    }

    float di = g_dinv[node];
    float sw = di * di;
    uint4 sv = __ldg((const uint4*)(h + (size_t)node * (HID_DIM / 2)) + lane);
    float4 bia0 = __ldg((const float4*)b1 + 2 * lane);
    float4 bia1 = __ldg((const float4*)b1 + 2 * lane + 1);

    float r0 = fmaxf(di * acc[0] + sw * bf_lo(sv.x) + bia0.x, 0.f);
    float r1 = fmaxf(di * acc[1] + sw * bf_hi(sv.x) + bia0.y, 0.f);
    float r2 = fmaxf(di * acc[2] + sw * bf_lo(sv.y) + bia0.z, 0.f);
    float r3 = fmaxf(di * acc[3] + sw * bf_hi(sv.y) + bia0.w, 0.f);
    float r4 = fmaxf(di * acc[4] + sw * bf_lo(sv.z) + bia1.x, 0.f);
    float r5 = fmaxf(di * acc[5] + sw * bf_hi(sv.z) + bia1.y, 0.f);
    float r6 = fmaxf(di * acc[6] + sw * bf_lo(sv.w) + bia1.z, 0.f);
    float r7 = fmaxf(di * acc[7] + sw * bf_hi(sv.w) + bia1.w, 0.f);

    uint4 rv;
    rv.x = pack_bf162(r0, r1);
    rv.y = pack_bf162(r2, r3);
    rv.z = pack_bf162(r4, r5);
    rv.w = pack_bf162(r6, r7);
    ((uint4*)(outb + (size_t)node * (HID_DIM / 2)))[lane] = rv;
}

// ------------------------------------------------------------------
// Layer-2 aggregation (bf16 gather, 4-edge unroll) + bias + log_softmax
// ------------------------------------------------------------------
__global__ void spmm_softmax_bf16(const uint32_t* __restrict__ h, float* __restrict__ out,
                                  const float* __restrict__ b2) {
    const int node = (blockIdx.x * blockDim.x + threadIdx.x) >> 5;
    const int lane = threadIdx.x & 31;
    if (node >= N_NODES) return;

    const int beg = g_rowptr[node];
    const int end = g_rowptr[node + 1];

    float a0 = 0.f, a1 = 0.f;
    int e = beg;
    for (; e + 3 < end; e += 4) {
        int s0 = __ldg(&g_esrc[e]);
        int s1 = __ldg(&g_esrc[e + 1]);
        int s2 = __ldg(&g_esrc[e + 2]);
        int s3 = __ldg(&g_esrc[e + 3]);
        float w0 = __ldg(&g_dinv[s0]);
        float w1 = __ldg(&g_dinv[s1]);
        float w2 = __ldg(&g_dinv[s2]);
        float w3 = __ldg(&g_dinv[s3]);
        uint32_t v0 = __ldg(h + (size_t)s0 * (OUT_DIM / 2) + lane);
        uint32_t v1 = __ldg(h + (size_t)s1 * (OUT_DIM / 2) + lane);
        uint32_t v2 = __ldg(h + (size_t)s2 * (OUT_DIM / 2) + lane);
        uint32_t v3 = __ldg(h + (size_t)s3 * (OUT_DIM / 2) + lane);
        a0 += w0 * bf_lo(v0) + w1 * bf_lo(v1) + w2 * bf_lo(v2) + w3 * bf_lo(v3);
        a1 += w0 * bf_hi(v0) + w1 * bf_hi(v1) + w2 * bf_hi(v2) + w3 * bf_hi(v3);
    }
    for (; e < end; e++) {
        int s0 = __ldg(&g_esrc[e]);
        float w0 = __ldg(&g_dinv[s0]);
        uint32_t v0 = __ldg(h + (size_t)s0 * (OUT_DIM / 2) + lane);
        a0 += w0 * bf_lo(v0);
        a1 += w0 * bf_hi(v0);
    }

    float di = g_dinv[node];
    float sw = di * di;
    uint32_t sv = __ldg(h + (size_t)node * (OUT_DIM / 2) + lane);
    float2 bias = __ldg((const float2*)b2 + lane);
    float v0 = di * a0 + sw * bf_lo(sv) + bias.x;
    float v1 = di * a1 + sw * bf_hi(sv) + bias.y;

    float m = fmaxf(v0, v1);
#pragma unroll
    for (int o = 16; o; o >>= 1) m = fmaxf(m, __shfl_xor_sync(0xFFFFFFFFu, m, o));
    float s = expf(v0 - m) + expf(v1 - m);
#pragma unroll
    for (int o = 16; o; o >>= 1) s += __shfl_xor_sync(0xFFFFFFFFu, s, o);
    float ls = m + logf(s);

    ((float2*)(out + (size_t)node * OUT_DIM))[lane] = make_float2(v0 - ls, v1 - ls);
}

// ------------------------------------------------------------------
extern "C" void kernel_launch(void* const* d_in, const int* in_sizes, int n_in,
                              void* d_out, int out_size) {
    const float* x  = (const float*)d_in[0];
    const float* W1 = (const float*)d_in[1];
    const float* b1 = (const float*)d_in[2];
    const float* W2 = (const float*)d_in[3];
    const float* b2 = (const float*)d_in[4];
    const int* ei   = (const int*)d_in[5];
    const int E = in_sizes[5] / 2;
    const int* src = ei;
    const int* dst = ei + E;
    float* out = (float*)d_out;

    uint32_t *h1b, *a1b, *h2b;
    int* cntp;
    cudaGetSymbolAddress((void**)&h1b, g_h1b);
    cudaGetSymbolAddress((void**)&a1b, g_a1b);
    cudaGetSymbolAddress((void**)&h2b, g_h2b);
    cudaGetSymbolAddress((void**)&cntp, g_cnt);

    // Host-side stream/events, created once on the (non-captured) correctness
    // call. Capture-legal fork/join pattern thereafter.
    static cudaStream_t s_side = nullptr;
    static cudaEvent_t s_evFork = nullptr, s_evJoin = nullptr;
    if (s_side == nullptr) {
        cudaStreamCreateWithFlags(&s_side, cudaStreamNonBlocking);
        cudaEventCreateWithFlags(&s_evFork, cudaEventDisableTiming);
        cudaEventCreateWithFlags(&s_evJoin, cudaEventDisableTiming);
    }

    const int TB = 256;

    // ---- fork: CSR build on side stream, GEMM1 on main stream ----
    cudaEventRecord(s_evFork, 0);
    cudaStreamWaitEvent(s_side, s_evFork, 0);

    cudaMemsetAsync(cntp, 0, N_NODES * sizeof(int), s_side);
    count_kernel<<<(E + TB - 1) / TB, TB, 0, s_side>>>(dst, E);
    scan1_kernel<<<SCAN_NBLK, SCAN_TB, 0, s_side>>>();       // also computes dinv
    scan2_kernel<<<1, SCAN_TB, 0, s_side>>>();
    scan3_kernel<<<SCAN_NBLK, SCAN_TB, 0, s_side>>>();
    fill_kernel<<<(E + TB - 1) / TB, TB, 0, s_side>>>(src, dst, E);
    cudaEventRecord(s_evJoin, s_side);

    // main stream: h1 = bf16(x @ W1), independent of CSR
    gemm1_bf16_mma<<<dim3(HID_DIM / 128, (N_NODES + 127) / 128), 256>>>(
        x, W1, h1b, N_NODES, HID_DIM, IN_DIM);

    // ---- join, then the dependent chain ----
    cudaStreamWaitEvent(0, s_evJoin, 0);
    spmm_relu_bf16<<<(N_NODES * 32 + TB - 1) / TB, TB>>>(h1b, a1b, b1);
    gemm2_bf16_mma<<<(N_NODES + 127) / 128, 256>>>(a1b, W2, h2b, N_NODES);
    spmm_softmax_bf16<<<(N_NODES * 32 + TB - 1) / TB, TB>>>(h2b, out, b2);
}